// round 3
// baseline (speedup 1.0000x reference)
#include <cuda_runtime.h>
#include <cuda_bf16.h>
#include <stdint.h>

// out[b] = sum_{s=0}^{199} w_weight[text[s,b]] + bias
// text (200, 2048) row-major, tokens in [0, 50000)
#define S_TOK 200
#define B_PHR 2048
#define V_SZ  50000
#define PHR_PER_BLK 16
#define NBLK (B_PHR / PHR_PER_BLK)    // 128 blocks (<=148 SMs, single wave)
#define NTHR 1024
#define NGRP 64                        // s-groups per phrase
// smem: table (50000 floats) + reduction (64*16 floats)
#define SMEM_FLOATS (V_SZ + NGRP * PHR_PER_BLK)
#define SMEM_BYTES  (SMEM_FLOATS * 4)

__global__ __launch_bounds__(NTHR, 1) void MNB_455266533601_kernel(
    const void* __restrict__ text_raw,
    const float* __restrict__ w_weight,
    const float* __restrict__ w_bias,
    float* __restrict__ out)
{
    extern __shared__ float smem[];
    float* sw  = smem;             // [V_SZ] staged weight table
    float* red = smem + V_SZ;      // [NGRP][PHR_PER_BLK] partials

    const int tid = threadIdx.x;
    const int p   = tid & (PHR_PER_BLK - 1);   // phrase within block
    const int g   = tid >> 4;                  // s-group 0..63
    const int b   = blockIdx.x * PHR_PER_BLK + p;

    // ---- dtype detection (fused): int64 buffers have zero odd 32-bit words ----
    const unsigned int* __restrict__ t32 = (const unsigned int*)text_raw;
    unsigned int probe = t32[2 * (tid & 31) + 1];
    const bool is64 = __all_sync(0xffffffffu, probe == 0u);

    // s-groups 0..7 take 4 tokens, 8..63 take 3  (8*4 + 56*3 = 200)
    const int cnt = (g < 8) ? 4 : 3;
    const int s0  = (g < 8) ? g * 4 : 32 + (g - 8) * 3;

    // ---- issue coalesced index loads FIRST so their latency hides under the
    //      table fill below ----
    int idx[4];
    if (is64) {
        const long long* __restrict__ t = (const long long*)text_raw;
#pragma unroll
        for (int i = 0; i < 4; i++)
            if (i < cnt) idx[i] = (int)t[(size_t)(s0 + i) * B_PHR + b];
    } else {
        const int* __restrict__ t = (const int*)text_raw;
#pragma unroll
        for (int i = 0; i < 4; i++)
            if (i < cnt) idx[i] = t[(s0 + i) * B_PHR + b];
    }

    // ---- stage the 195KB weight table into shared memory (vectorized) ----
    {
        const float4* __restrict__ w4 = (const float4*)w_weight;
        float4* s4 = (float4*)sw;
#pragma unroll 4
        for (int i = tid; i < V_SZ / 4; i += NTHR)   // 12500 float4
            s4[i] = w4[i];
    }
    __syncthreads();

    // ---- gather from smem (LDS, ~4-way conflicts instead of 31 L1tex replays) ----
    float acc = 0.0f;
#pragma unroll
    for (int i = 0; i < 4; i++)
        if (i < cnt) acc += sw[idx[i]];

    // ---- reduce 64 s-group partials per phrase ----
    red[g * PHR_PER_BLK + p] = acc;
    __syncthreads();

    if (tid < PHR_PER_BLK) {
        float sum = 0.0f;
#pragma unroll
        for (int j = 0; j < NGRP; j++) sum += red[j * PHR_PER_BLK + tid];
        out[blockIdx.x * PHR_PER_BLK + tid] = sum + __ldg(w_bias);
    }
}

extern "C" void kernel_launch(void* const* d_in, const int* in_sizes, int n_in,
                              void* d_out, int out_size) {
    const void*  text   = d_in[0];                 // (200, 2048) int32 or int64
    const float* weight = (const float*)d_in[1];   // (1, 50000) float32
    const float* bias   = (const float*)d_in[2];   // (1,) float32
    float*       out    = (float*)d_out;           // (2048, 1) float32

    // >48KB dynamic smem needs the attribute bump (idempotent; not a stream op,
    // safe under graph capture).
    cudaFuncSetAttribute(MNB_455266533601_kernel,
                         cudaFuncAttributeMaxDynamicSharedMemorySize, SMEM_BYTES);

    MNB_455266533601_kernel<<<NBLK, NTHR, SMEM_BYTES>>>(text, weight, bias, out);
}

// round 4
// speedup vs baseline: 1.2651x; 1.2651x over previous
#include <cuda_runtime.h>
#include <cuda_bf16.h>
#include <stdint.h>

// out[b] = sum_{s=0}^{199} w_weight[text[s,b]] + bias
// text (200, 2048) row-major, tokens in [0, 50000)
#define S_TOK 200
#define B_PHR 2048
#define V_SZ  50000
#define PHR_PER_BLK 16
#define NBLK (B_PHR / PHR_PER_BLK)    // 128 blocks, single wave
#define NTHR 1024
#define NGRP 64                        // s-groups per phrase
#define TBL_BYTES (V_SZ * 4)           // 200000 B
#define CHUNK_BYTES 50000              // 4 chunks, each 16B-multiple
// smem: table + reduction partials + mbarrier (16B-aligned slot)
#define RED_FLOATS (NGRP * PHR_PER_BLK)
#define SMEM_BYTES (TBL_BYTES + RED_FLOATS * 4 + 16)

__device__ __forceinline__ uint32_t smem_u32(const void* p) {
    uint32_t a;
    asm("{ .reg .u64 t; cvta.to.shared.u64 t, %1; cvt.u32.u64 %0, t; }"
        : "=r"(a) : "l"(p));
    return a;
}

__global__ __launch_bounds__(NTHR, 1) void MNB_455266533601_kernel(
    const void* __restrict__ text_raw,
    const float* __restrict__ w_weight,
    const float* __restrict__ w_bias,
    float* __restrict__ out)
{
    extern __shared__ float smem[];
    float* sw  = smem;                       // [V_SZ] staged table (200000 B)
    float* red = smem + V_SZ;                // [NGRP][PHR_PER_BLK]
    // mbarrier after red, 8-byte aligned
    unsigned long long* mbar =
        (unsigned long long*)(smem + V_SZ + RED_FLOATS);

    const int tid = threadIdx.x;
    const int p   = tid & (PHR_PER_BLK - 1);   // phrase within block
    const int g   = tid >> 4;                  // s-group 0..63
    const int b   = blockIdx.x * PHR_PER_BLK + p;
    const uint32_t mbar_a = smem_u32(mbar);

    // ---- init mbarrier ----
    if (tid == 0) {
        asm volatile("mbarrier.init.shared.b64 [%0], 1;" :: "r"(mbar_a) : "memory");
    }
    __syncthreads();

    // ---- one thread kicks off the async TMA bulk fill of the table ----
    if (tid == 0) {
        asm volatile("mbarrier.arrive.expect_tx.shared.b64 _, [%0], %1;"
                     :: "r"(mbar_a), "r"((uint32_t)TBL_BYTES) : "memory");
        uint32_t dst = smem_u32(sw);
        const char* src = (const char*)w_weight;
#pragma unroll
        for (int c = 0; c < 4; c++) {
            asm volatile(
                "cp.async.bulk.shared::cta.global.mbarrier::complete_tx::bytes "
                "[%0], [%1], %2, [%3];"
                :: "r"(dst + c * CHUNK_BYTES),
                   "l"(src + c * CHUNK_BYTES),
                   "r"((uint32_t)CHUNK_BYTES),
                   "r"(mbar_a)
                : "memory");
        }
    }

    // ---- dtype detection (overlapped with the TMA fill) ----
    const unsigned int* __restrict__ t32 = (const unsigned int*)text_raw;
    unsigned int probe = t32[2 * (tid & 31) + 1];
    const bool is64 = __all_sync(0xffffffffu, probe == 0u);

    // s-groups 0..7 take 4 tokens, 8..63 take 3  (8*4 + 56*3 = 200)
    const int cnt = (g < 8) ? 4 : 3;
    const int s0  = (g < 8) ? g * 4 : 32 + (g - 8) * 3;

    // ---- coalesced index loads, fully overlapped with the TMA fill ----
    int idx[4];
    if (is64) {
        const long long* __restrict__ t = (const long long*)text_raw;
#pragma unroll
        for (int i = 0; i < 4; i++)
            if (i < cnt) idx[i] = (int)t[(size_t)(s0 + i) * B_PHR + b];
    } else {
        const int* __restrict__ t = (const int*)text_raw;
#pragma unroll
        for (int i = 0; i < 4; i++)
            if (i < cnt) idx[i] = t[(s0 + i) * B_PHR + b];
    }

    // ---- wait for the table (acquire orders subsequent LDS after TMA writes) ----
    {
        uint32_t done;
        asm volatile(
            "{\n\t.reg .pred P;\n\t"
            "mbarrier.try_wait.parity.acquire.cta.shared::cta.b64 P, [%1], 0;\n\t"
            "selp.b32 %0, 1, 0, P;\n\t}"
            : "=r"(done) : "r"(mbar_a) : "memory");
        if (!done) {
            asm volatile(
                "{\n\t.reg .pred P;\n\t"
                "WL_%=:\n\t"
                "mbarrier.try_wait.parity.acquire.cta.shared::cta.b64 P, [%0], 0, 0x989680;\n\t"
                "@P bra.uni WD_%=;\n\t"
                "bra.uni WL_%=;\n\t"
                "WD_%=:\n\t}"
                :: "r"(mbar_a) : "memory");
        }
    }

    // ---- gather from smem ----
    float acc = 0.0f;
#pragma unroll
    for (int i = 0; i < 4; i++)
        if (i < cnt) acc += sw[idx[i]];

    // ---- reduce 64 partials per phrase ----
    red[g * PHR_PER_BLK + p] = acc;
    __syncthreads();

    if (tid < PHR_PER_BLK) {
        float sum = 0.0f;
#pragma unroll
        for (int j = 0; j < NGRP; j++) sum += red[j * PHR_PER_BLK + tid];
        out[blockIdx.x * PHR_PER_BLK + tid] = sum + __ldg(w_bias);
    }
}

extern "C" void kernel_launch(void* const* d_in, const int* in_sizes, int n_in,
                              void* d_out, int out_size) {
    const void*  text   = d_in[0];                 // (200, 2048) int32 or int64
    const float* weight = (const float*)d_in[1];   // (1, 50000) float32
    const float* bias   = (const float*)d_in[2];   // (1,) float32
    float*       out    = (float*)d_out;           // (2048, 1) float32

    cudaFuncSetAttribute(MNB_455266533601_kernel,
                         cudaFuncAttributeMaxDynamicSharedMemorySize, SMEM_BYTES);

    MNB_455266533601_kernel<<<NBLK, NTHR, SMEM_BYTES>>>(text, weight, bias, out);
}

// round 5
// speedup vs baseline: 1.3140x; 1.0386x over previous
#include <cuda_runtime.h>
#include <cuda_bf16.h>
#include <stdint.h>

// out[b] = sum_{s=0}^{199} w_weight[text[s,b]] + bias
// text (200, 2048) row-major, tokens in [0, 50000)
#define S_TOK 200
#define B_PHR 2048
#define V_SZ  50000
#define PHR_PER_BLK 32
#define NBLK (B_PHR / PHR_PER_BLK)    // 64 blocks
#define NTHR 1024
#define NGRP 32                        // s-groups per phrase (32 threads each... no: 32 groups x 32 phrases)
#define TBL_BYTES (V_SZ * 4)           // 200000 B
#define CHUNK_BYTES 50000              // 4 chunks, each 16B-multiple
#define RED_FLOATS (NGRP * PHR_PER_BLK)
#define SMEM_BYTES (TBL_BYTES + RED_FLOATS * 4 + 16)

__device__ __forceinline__ uint32_t smem_u32(const void* p) {
    uint32_t a;
    asm("{ .reg .u64 t; cvta.to.shared.u64 t, %1; cvt.u32.u64 %0, t; }"
        : "=r"(a) : "l"(p));
    return a;
}

__global__ __launch_bounds__(NTHR, 1) void MNB_455266533601_kernel(
    const void* __restrict__ text_raw,
    const float* __restrict__ w_weight,
    const float* __restrict__ w_bias,
    float* __restrict__ out)
{
    extern __shared__ float smem[];
    float* sw  = smem;                       // [V_SZ] staged table
    float* red = smem + V_SZ;                // [NGRP][PHR_PER_BLK]
    unsigned long long* mbar =
        (unsigned long long*)(smem + V_SZ + RED_FLOATS);

    const int tid = threadIdx.x;
    const int p   = tid & (PHR_PER_BLK - 1);   // phrase within block (0..31)
    const int g   = tid >> 5;                  // s-group (0..31)
    const int b   = blockIdx.x * PHR_PER_BLK + p;
    const uint32_t mbar_a = smem_u32(mbar);

    // ---- init mbarrier, then kick the async bulk fill from one thread ----
    if (tid == 0) {
        asm volatile("mbarrier.init.shared.b64 [%0], 1;" :: "r"(mbar_a) : "memory");
    }
    __syncthreads();

    if (tid == 0) {
        asm volatile("mbarrier.arrive.expect_tx.shared.b64 _, [%0], %1;"
                     :: "r"(mbar_a), "r"((uint32_t)TBL_BYTES) : "memory");
        uint32_t dst = smem_u32(sw);
        const char* src = (const char*)w_weight;
#pragma unroll
        for (int c = 0; c < 4; c++) {
            asm volatile(
                "cp.async.bulk.shared::cta.global.mbarrier::complete_tx::bytes "
                "[%0], [%1], %2, [%3];"
                :: "r"(dst + c * CHUNK_BYTES),
                   "l"(src + c * CHUNK_BYTES),
                   "r"((uint32_t)CHUNK_BYTES),
                   "r"(mbar_a)
                : "memory");
        }
    }

    // ---- dtype detection (overlapped with the TMA fill) ----
    // int64 little-endian buffers have zero odd 32-bit words; tokens < 50000.
    const unsigned int* __restrict__ t32 = (const unsigned int*)text_raw;
    unsigned int probe = t32[2 * (tid & 31) + 1];
    const bool is64 = __all_sync(0xffffffffu, probe == 0u);

    // s-groups 0..7 take 7 tokens, 8..31 take 6  (8*7 + 24*6 = 200)
    const int cnt = (g < 8) ? 7 : 6;
    const int s0  = (g < 8) ? g * 7 : 56 + (g - 8) * 6;

    // ---- coalesced index loads, fully overlapped with the TMA fill ----
    int idx[7];
    if (is64) {
        const long long* __restrict__ t = (const long long*)text_raw;
#pragma unroll
        for (int i = 0; i < 7; i++)
            if (i < cnt) idx[i] = (int)t[(size_t)(s0 + i) * B_PHR + b];
    } else {
        const int* __restrict__ t = (const int*)text_raw;
#pragma unroll
        for (int i = 0; i < 7; i++)
            if (i < cnt) idx[i] = t[(s0 + i) * B_PHR + b];
    }

    // ---- wait for the table (acquire orders the LDS gathers after TMA writes) ----
    {
        uint32_t done;
        asm volatile(
            "{\n\t.reg .pred P;\n\t"
            "mbarrier.try_wait.parity.acquire.cta.shared::cta.b64 P, [%1], 0;\n\t"
            "selp.b32 %0, 1, 0, P;\n\t}"
            : "=r"(done) : "r"(mbar_a) : "memory");
        if (!done) {
            asm volatile(
                "{\n\t.reg .pred P;\n\t"
                "WL_%=:\n\t"
                "mbarrier.try_wait.parity.acquire.cta.shared::cta.b64 P, [%0], 0, 0x989680;\n\t"
                "@P bra.uni WD_%=;\n\t"
                "bra.uni WL_%=;\n\t"
                "WD_%=:\n\t}"
                :: "r"(mbar_a) : "memory");
        }
    }

    // ---- gather from smem ----
    float acc = 0.0f;
#pragma unroll
    for (int i = 0; i < 7; i++)
        if (i < cnt) acc += sw[idx[i]];

    // ---- reduce 32 partials per phrase ----
    red[g * PHR_PER_BLK + p] = acc;
    __syncthreads();

    if (tid < PHR_PER_BLK) {
        float sum = 0.0f;
#pragma unroll
        for (int j = 0; j < NGRP; j++) sum += red[j * PHR_PER_BLK + tid];
        out[blockIdx.x * PHR_PER_BLK + tid] = sum + __ldg(w_bias);
    }
}

extern "C" void kernel_launch(void* const* d_in, const int* in_sizes, int n_in,
                              void* d_out, int out_size) {
    const void*  text   = d_in[0];                 // (200, 2048) int32 or int64
    const float* weight = (const float*)d_in[1];   // (1, 50000) float32
    const float* bias   = (const float*)d_in[2];   // (1,) float32
    float*       out    = (float*)d_out;           // (2048, 1) float32

    cudaFuncSetAttribute(MNB_455266533601_kernel,
                         cudaFuncAttributeMaxDynamicSharedMemorySize, SMEM_BYTES);

    MNB_455266533601_kernel<<<NBLK, NTHR, SMEM_BYTES>>>(text, weight, bias, out);
}